// round 1
// baseline (speedup 1.0000x reference)
#include <cuda_runtime.h>
#include <cstdint>

#define H_DIM 1024
#define I_DIM 512
#define E_NUM 8
#define N_TOK 8192
#define SCALE_F 2.5f

// Scratch (allocation-free rule: __device__ globals)
__device__ float g_A[(size_t)N_TOK * I_DIM];   // intermediate silu(g)*u for current expert
__device__ float g_cw[(size_t)N_TOK * E_NUM];  // dense combine weights

// ---------------------------------------------------------------------------
// helpers
// ---------------------------------------------------------------------------
__device__ __forceinline__ float tf32r(float f) {
    uint32_t u;
    asm("cvt.rna.tf32.f32 %0, %1;" : "=r"(u) : "f"(f));
    return __uint_as_float(u);
}

__device__ __forceinline__ void mma_tf32(float c[4], const uint32_t a[4], const uint32_t b[2]) {
    asm volatile(
        "mma.sync.aligned.m16n8k8.row.col.f32.tf32.tf32.f32 "
        "{%0,%1,%2,%3}, {%4,%5,%6,%7}, {%8,%9}, {%0,%1,%2,%3};\n"
        : "+f"(c[0]), "+f"(c[1]), "+f"(c[2]), "+f"(c[3])
        : "r"(a[0]), "r"(a[1]), "r"(a[2]), "r"(a[3]), "r"(b[0]), "r"(b[1]));
}

// ---------------------------------------------------------------------------
// Router: logits -> sigmoid -> group top-2 -> top-2 groups -> weights
// One warp per token. blockDim = (32, 8)
// ---------------------------------------------------------------------------
__global__ void router_kernel(const float* __restrict__ x,
                              const float* __restrict__ gate_w,
                              const float* __restrict__ bias) {
    int token = blockIdx.x * 8 + threadIdx.y;
    int lane = threadIdx.x;
    const float* xr = x + (size_t)token * H_DIM;

    float logits[E_NUM];
#pragma unroll
    for (int e = 0; e < E_NUM; e++) {
        const float* w = gate_w + (size_t)e * H_DIM;
        float s = 0.f;
        for (int h = lane; h < H_DIM; h += 32) s += xr[h] * w[h];
#pragma unroll
        for (int o = 16; o; o >>= 1) s += __shfl_xor_sync(0xffffffffu, s, o);
        logits[e] = s;
    }

    if (lane == 0) {
        float sc[E_NUM], scc[E_NUM];
#pragma unroll
        for (int e = 0; e < E_NUM; e++) {
            sc[e] = 1.f / (1.f + expf(-logits[e]));
            scc[e] = sc[e] + bias[e];
        }
        // group score = sum of both members (E/NG == 2 => top2 of group = all)
        float gs[4];
#pragma unroll
        for (int g = 0; g < 4; g++) gs[g] = scc[2 * g] + scc[2 * g + 1];
        // top-2 groups (jax top_k tie -> lower index; use strict >)
        int g1 = 0;
#pragma unroll
        for (int g = 1; g < 4; g++) if (gs[g] > gs[g1]) g1 = g;
        int g2 = -1;
#pragma unroll
        for (int g = 0; g < 4; g++) {
            if (g == g1) continue;
            if (g2 < 0 || gs[g] > gs[g2]) g2 = g;
        }
        float w[E_NUM];
        float wsum = 0.f;
#pragma unroll
        for (int e = 0; e < E_NUM; e++) {
            int g = e >> 1;
            bool sel = (g == g1) || (g == g2);
            w[e] = sel ? sc[e] : 0.f;
            wsum += w[e];
        }
        float inv = SCALE_F / (wsum + 1e-20f);
#pragma unroll
        for (int e = 0; e < E_NUM; e++)
            g_cw[(size_t)token * E_NUM + e] = w[e] * inv;
    }
}

// ---------------------------------------------------------------------------
// GEMM1 (dual): A[n][i] = silu(X@Wg)[n][i] * (X@Wu)[n][i]
// M = 8192 tokens, K = 1024, N = 512. Tiles: 128x64x32, 256 threads (8 warps).
// Warp: 32x32 sub-tile -> 2 m-frags x 4 n-frags of m16n8k8 tf32.
// ---------------------------------------------------------------------------
__global__ void __launch_bounds__(256) gemm1_kernel(const float* __restrict__ X,
                                                    const float* __restrict__ Wg,
                                                    const float* __restrict__ Wu) {
    __shared__ float As[128][36];   // stride 36 -> conflict-free frag loads
    __shared__ float Bg[32][72];    // stride 72 -> conflict-free frag loads
    __shared__ float Bu[32][72];

    int tid = threadIdx.x;
    int bm = blockIdx.y, bn = blockIdx.x;
    int warp = tid >> 5, lane = tid & 31;
    int wm = warp & 3, wn = warp >> 2;

    float accG[2][4][4], accU[2][4][4];
#pragma unroll
    for (int i = 0; i < 2; i++)
#pragma unroll
        for (int j = 0; j < 4; j++)
#pragma unroll
            for (int k = 0; k < 4; k++) { accG[i][j][k] = 0.f; accU[i][j][k] = 0.f; }

    const float* Xb = X + (size_t)bm * 128 * H_DIM;
    const float* Wgb = Wg + bn * 64;
    const float* Wub = Wu + bn * 64;

    for (int kt = 0; kt < H_DIM / 32; kt++) {
        int k0 = kt * 32;
        // load X tile 128x32
#pragma unroll
        for (int i = 0; i < 4; i++) {
            int slot = tid + 256 * i;
            int r = slot >> 3, c = (slot & 7) * 4;
            float4 v = *(const float4*)(Xb + (size_t)r * H_DIM + k0 + c);
            v.x = tf32r(v.x); v.y = tf32r(v.y); v.z = tf32r(v.z); v.w = tf32r(v.w);
            *(float4*)&As[r][c] = v;
        }
        // load W tiles 32x64 (gate + up)
#pragma unroll
        for (int i = 0; i < 2; i++) {
            int slot = tid + 256 * i;
            int r = slot >> 4, c = (slot & 15) * 4;
            float4 vg = *(const float4*)(Wgb + (size_t)(k0 + r) * I_DIM + c);
            vg.x = tf32r(vg.x); vg.y = tf32r(vg.y); vg.z = tf32r(vg.z); vg.w = tf32r(vg.w);
            *(float4*)&Bg[r][c] = vg;
            float4 vu = *(const float4*)(Wub + (size_t)(k0 + r) * I_DIM + c);
            vu.x = tf32r(vu.x); vu.y = tf32r(vu.y); vu.z = tf32r(vu.z); vu.w = tf32r(vu.w);
            *(float4*)&Bu[r][c] = vu;
        }
        __syncthreads();

#pragma unroll
        for (int ks = 0; ks < 4; ks++) {
            int kc = ks * 8 + (lane & 3);
            int r0 = wm * 32 + (lane >> 2);
            uint32_t a[2][4];
#pragma unroll
            for (int mt = 0; mt < 2; mt++) {
                int rb = r0 + mt * 16;
                a[mt][0] = __float_as_uint(As[rb][kc]);
                a[mt][1] = __float_as_uint(As[rb + 8][kc]);
                a[mt][2] = __float_as_uint(As[rb][kc + 4]);
                a[mt][3] = __float_as_uint(As[rb + 8][kc + 4]);
            }
            int nb = wn * 32 + (lane >> 2);
#pragma unroll
            for (int nt = 0; nt < 4; nt++) {
                int nc = nb + nt * 8;
                uint32_t bg[2], bu[2];
                bg[0] = __float_as_uint(Bg[kc][nc]);
                bg[1] = __float_as_uint(Bg[kc + 4][nc]);
                bu[0] = __float_as_uint(Bu[kc][nc]);
                bu[1] = __float_as_uint(Bu[kc + 4][nc]);
                mma_tf32(accG[0][nt], a[0], bg);
                mma_tf32(accG[1][nt], a[1], bg);
                mma_tf32(accU[0][nt], a[0], bu);
                mma_tf32(accU[1][nt], a[1], bu);
            }
        }
        __syncthreads();
    }

    // epilogue: silu(g) * u -> scratch A
#pragma unroll
    for (int mt = 0; mt < 2; mt++) {
#pragma unroll
        for (int nt = 0; nt < 4; nt++) {
            int row = bm * 128 + wm * 32 + mt * 16 + (lane >> 2);
            int col = bn * 64 + wn * 32 + nt * 8 + (lane & 3) * 2;
#pragma unroll
            for (int h = 0; h < 2; h++) {
                int rr = row + h * 8;
#pragma unroll
                for (int j = 0; j < 2; j++) {
                    float g = accG[mt][nt][h * 2 + j];
                    float u = accU[mt][nt][h * 2 + j];
                    float s = (g / (1.f + expf(-g))) * u;   // silu(g)*u
                    g_A[(size_t)rr * I_DIM + col + j] = s;
                }
            }
        }
    }
}

// ---------------------------------------------------------------------------
// GEMM2: out[n][h] (+)= cw[n][e] * (A @ Wd)[n][h]
// M = 8192, K = 512, N = 1024.
// ---------------------------------------------------------------------------
template <bool ACCUM>
__global__ void __launch_bounds__(256) gemm2_kernel(const float* __restrict__ Wd,
                                                    int expert,
                                                    float* __restrict__ out) {
    __shared__ float As[128][36];
    __shared__ float Bs[32][72];

    int tid = threadIdx.x;
    int bm = blockIdx.y, bn = blockIdx.x;
    int warp = tid >> 5, lane = tid & 31;
    int wm = warp & 3, wn = warp >> 2;

    float acc[2][4][4];
#pragma unroll
    for (int i = 0; i < 2; i++)
#pragma unroll
        for (int j = 0; j < 4; j++)
#pragma unroll
            for (int k = 0; k < 4; k++) acc[i][j][k] = 0.f;

    const float* Ab = g_A + (size_t)bm * 128 * I_DIM;
    const float* Wb = Wd + bn * 64;

    for (int kt = 0; kt < I_DIM / 32; kt++) {
        int k0 = kt * 32;
#pragma unroll
        for (int i = 0; i < 4; i++) {
            int slot = tid + 256 * i;
            int r = slot >> 3, c = (slot & 7) * 4;
            float4 v = *(const float4*)(Ab + (size_t)r * I_DIM + k0 + c);
            v.x = tf32r(v.x); v.y = tf32r(v.y); v.z = tf32r(v.z); v.w = tf32r(v.w);
            *(float4*)&As[r][c] = v;
        }
#pragma unroll
        for (int i = 0; i < 2; i++) {
            int slot = tid + 256 * i;
            int r = slot >> 4, c = (slot & 15) * 4;
            float4 v = *(const float4*)(Wb + (size_t)(k0 + r) * H_DIM + c);
            v.x = tf32r(v.x); v.y = tf32r(v.y); v.z = tf32r(v.z); v.w = tf32r(v.w);
            *(float4*)&Bs[r][c] = v;
        }
        __syncthreads();

#pragma unroll
        for (int ks = 0; ks < 4; ks++) {
            int kc = ks * 8 + (lane & 3);
            int r0 = wm * 32 + (lane >> 2);
            uint32_t a[2][4];
#pragma unroll
            for (int mt = 0; mt < 2; mt++) {
                int rb = r0 + mt * 16;
                a[mt][0] = __float_as_uint(As[rb][kc]);
                a[mt][1] = __float_as_uint(As[rb + 8][kc]);
                a[mt][2] = __float_as_uint(As[rb][kc + 4]);
                a[mt][3] = __float_as_uint(As[rb + 8][kc + 4]);
            }
            int nb = wn * 32 + (lane >> 2);
#pragma unroll
            for (int nt = 0; nt < 4; nt++) {
                int nc = nb + nt * 8;
                uint32_t b[2];
                b[0] = __float_as_uint(Bs[kc][nc]);
                b[1] = __float_as_uint(Bs[kc + 4][nc]);
                mma_tf32(acc[0][nt], a[0], b);
                mma_tf32(acc[1][nt], a[1], b);
            }
        }
        __syncthreads();
    }

#pragma unroll
    for (int mt = 0; mt < 2; mt++) {
#pragma unroll
        for (int h = 0; h < 2; h++) {
            int rr = bm * 128 + wm * 32 + mt * 16 + (lane >> 2) + h * 8;
            float s = ACCUM ? g_cw[(size_t)rr * E_NUM + expert] : 1.0f;
#pragma unroll
            for (int nt = 0; nt < 4; nt++) {
                int col = bn * 64 + wn * 32 + nt * 8 + (lane & 3) * 2;
#pragma unroll
                for (int j = 0; j < 2; j++) {
                    float v = s * acc[mt][nt][h * 2 + j];
                    size_t idx = (size_t)rr * H_DIM + col + j;
                    if (ACCUM) out[idx] += v;
                    else out[idx] = v;
                }
            }
        }
    }
}

// ---------------------------------------------------------------------------
extern "C" void kernel_launch(void* const* d_in, const int* in_sizes, int n_in,
                              void* d_out, int out_size) {
    const float* x      = (const float*)d_in[0];
    const float* gate_w = (const float*)d_in[1];
    const float* bias   = (const float*)d_in[2];
    const float* Wg     = (const float*)d_in[3];
    const float* Wu     = (const float*)d_in[4];
    const float* Wd     = (const float*)d_in[5];
    const float* Wg_s   = (const float*)d_in[6];
    const float* Wu_s   = (const float*)d_in[7];
    const float* Wd_s   = (const float*)d_in[8];
    float* out = (float*)d_out;

    router_kernel<<<N_TOK / 8, dim3(32, 8)>>>(x, gate_w, bias);

    dim3 g1(I_DIM / 64, N_TOK / 128);
    dim3 g2(H_DIM / 64, N_TOK / 128);

    // shared expert first (overwrites poisoned d_out)
    gemm1_kernel<<<g1, 256>>>(x, Wg_s, Wu_s);
    gemm2_kernel<false><<<g2, 256>>>(Wd_s, 0, out);

    // routed experts accumulate
    for (int e = 0; e < E_NUM; e++) {
        gemm1_kernel<<<g1, 256>>>(x, Wg + (size_t)e * H_DIM * I_DIM,
                                  Wu + (size_t)e * H_DIM * I_DIM);
        gemm2_kernel<true><<<g2, 256>>>(Wd + (size_t)e * I_DIM * H_DIM, e, out);
    }
}

// round 2
// speedup vs baseline: 2.1115x; 2.1115x over previous
#include <cuda_runtime.h>
#include <cstdint>

#define H_DIM 1024
#define I_DIM 512
#define E_NUM 8
#define N_TOK 8192
#define SCALE_F 2.5f

// Scratch (allocation-free rule: __device__ globals)
__device__ float g_A[(size_t)N_TOK * I_DIM];   // silu(g)*u for current expert (gathered rows)
__device__ float g_cw[(size_t)N_TOK * E_NUM];  // dense combine weights
__device__ int   g_idx[E_NUM * N_TOK];         // per-expert gathered token lists
__device__ int   g_cnt[E_NUM];                 // per-expert token counts

// ---------------------------------------------------------------------------
// helpers
// ---------------------------------------------------------------------------
__device__ __forceinline__ float tf32r(float f) {
    uint32_t u;
    asm("cvt.rna.tf32.f32 %0, %1;" : "=r"(u) : "f"(f));
    return __uint_as_float(u);
}

__device__ __forceinline__ void mma_tf32(float c[4], const uint32_t a[4], const uint32_t b[2]) {
    asm volatile(
        "mma.sync.aligned.m16n8k8.row.col.f32.tf32.tf32.f32 "
        "{%0,%1,%2,%3}, {%4,%5,%6,%7}, {%8,%9}, {%0,%1,%2,%3};\n"
        : "+f"(c[0]), "+f"(c[1]), "+f"(c[2]), "+f"(c[3])
        : "r"(a[0]), "r"(a[1]), "r"(a[2]), "r"(a[3]), "r"(b[0]), "r"(b[1]));
}

__device__ __forceinline__ void cp_async16(float* smem, const float* gmem) {
    uint32_t s = (uint32_t)__cvta_generic_to_shared(smem);
    asm volatile("cp.async.cg.shared.global [%0], [%1], 16;\n" :: "r"(s), "l"(gmem));
}
__device__ __forceinline__ void cp_commit() { asm volatile("cp.async.commit_group;\n"); }
template <int N>
__device__ __forceinline__ void cp_wait() { asm volatile("cp.async.wait_group %0;\n" :: "n"(N)); }

// ---------------------------------------------------------------------------
__global__ void zero_cnt_kernel() {
    if (threadIdx.x < E_NUM) g_cnt[threadIdx.x] = 0;
}

// ---------------------------------------------------------------------------
// Router: logits -> sigmoid -> group top-2 -> weights + gather lists
// One warp per token. blockDim = (32, 8)
// ---------------------------------------------------------------------------
__global__ void router_kernel(const float* __restrict__ x,
                              const float* __restrict__ gate_w,
                              const float* __restrict__ bias) {
    int token = blockIdx.x * 8 + threadIdx.y;
    int lane = threadIdx.x;
    const float* xr = x + (size_t)token * H_DIM;

    float logits[E_NUM];
#pragma unroll
    for (int e = 0; e < E_NUM; e++) {
        const float* w = gate_w + (size_t)e * H_DIM;
        float s = 0.f;
        for (int h = lane; h < H_DIM; h += 32) s += xr[h] * w[h];
#pragma unroll
        for (int o = 16; o; o >>= 1) s += __shfl_xor_sync(0xffffffffu, s, o);
        logits[e] = s;
    }

    if (lane == 0) {
        float sc[E_NUM], scc[E_NUM];
#pragma unroll
        for (int e = 0; e < E_NUM; e++) {
            sc[e] = 1.f / (1.f + expf(-logits[e]));
            scc[e] = sc[e] + bias[e];
        }
        float gs[4];
#pragma unroll
        for (int g = 0; g < 4; g++) gs[g] = scc[2 * g] + scc[2 * g + 1];
        int g1 = 0;
#pragma unroll
        for (int g = 1; g < 4; g++) if (gs[g] > gs[g1]) g1 = g;
        int g2 = -1;
#pragma unroll
        for (int g = 0; g < 4; g++) {
            if (g == g1) continue;
            if (g2 < 0 || gs[g] > gs[g2]) g2 = g;
        }
        float w[E_NUM];
        float wsum = 0.f;
        bool sel[E_NUM];
#pragma unroll
        for (int e = 0; e < E_NUM; e++) {
            int g = e >> 1;
            sel[e] = (g == g1) || (g == g2);
            w[e] = sel[e] ? sc[e] : 0.f;
            wsum += w[e];
        }
        float inv = SCALE_F / (wsum + 1e-20f);
#pragma unroll
        for (int e = 0; e < E_NUM; e++) {
            g_cw[(size_t)token * E_NUM + e] = w[e] * inv;
            if (sel[e]) {
                int p = atomicAdd(&g_cnt[e], 1);
                g_idx[e * N_TOK + p] = token;
            }
        }
    }
}

// ---------------------------------------------------------------------------
// GEMM1 (dual, gathered): A[gm][i] = silu(X[tok]@Wg)[i] * (X[tok]@Wu)[i]
// Tiles 128x64x32, 256 threads, cp.async 2-stage pipeline.
// ---------------------------------------------------------------------------
template <bool GATHER>
__global__ void __launch_bounds__(256) gemm1_kernel(const float* __restrict__ X,
                                                    const float* __restrict__ Wg,
                                                    const float* __restrict__ Wu,
                                                    int expert) {
    int cnt = GATHER ? g_cnt[expert] : N_TOK;
    int bm = blockIdx.y, bn = blockIdx.x;
    if (bm * 128 >= cnt) return;

    extern __shared__ float sm[];
    float* AsB = sm;                    // [2][128][36]
    float* BgB = sm + 2 * 128 * 36;     // [2][32][72]
    float* BuB = BgB + 2 * 32 * 72;     // [2][32][72]

    int tid = threadIdx.x, warp = tid >> 5, lane = tid & 31;
    int wm = warp & 3, wn = warp >> 2;

    const int* idx = g_idx + expert * N_TOK;
    int cbase = (tid & 7) * 4;
    const float* xrow[4];
#pragma unroll
    for (int i = 0; i < 4; i++) {
        int r = (tid >> 3) + 32 * i;
        int gm = bm * 128 + r;
        int gg = gm < cnt ? gm : cnt - 1;
        int tok = GATHER ? idx[gg] : gg;
        xrow[i] = X + (size_t)tok * H_DIM + cbase;
    }
    int wr = tid >> 4;           // 0..15
    int wc = (tid & 15) * 4;     // 0..60
    const float* wg0 = Wg + bn * 64 + wc;
    const float* wu0 = Wu + bn * 64 + wc;

    float accG[2][4][4] = {}, accU[2][4][4] = {};

    auto issue = [&](int kt) {
        int st = kt & 1;
        float* a = AsB + st * 128 * 36;
#pragma unroll
        for (int i = 0; i < 4; i++) {
            int r = (tid >> 3) + 32 * i;
            cp_async16(a + r * 36 + cbase, xrow[i] + kt * 32);
        }
        float* bg = BgB + st * 32 * 72;
        float* bu = BuB + st * 32 * 72;
#pragma unroll
        for (int i = 0; i < 2; i++) {
            int r = wr + 16 * i;
            cp_async16(bg + r * 72 + wc, wg0 + (size_t)(kt * 32 + r) * I_DIM);
            cp_async16(bu + r * 72 + wc, wu0 + (size_t)(kt * 32 + r) * I_DIM);
        }
        cp_commit();
    };

    issue(0);
    const int KT = H_DIM / 32;
    for (int kt = 0; kt < KT; kt++) {
        if (kt + 1 < KT) { issue(kt + 1); cp_wait<1>(); }
        else             { cp_wait<0>(); }
        __syncthreads();
        int st = kt & 1;
        const float* a_ = AsB + st * 128 * 36;
        const float* bg_ = BgB + st * 32 * 72;
        const float* bu_ = BuB + st * 32 * 72;
#pragma unroll
        for (int ks = 0; ks < 4; ks++) {
            int kc = ks * 8 + (lane & 3);
            int r0 = wm * 32 + (lane >> 2);
            uint32_t a[2][4];
#pragma unroll
            for (int mt = 0; mt < 2; mt++) {
                int rb = r0 + mt * 16;
                a[mt][0] = __float_as_uint(tf32r(a_[rb * 36 + kc]));
                a[mt][1] = __float_as_uint(tf32r(a_[(rb + 8) * 36 + kc]));
                a[mt][2] = __float_as_uint(tf32r(a_[rb * 36 + kc + 4]));
                a[mt][3] = __float_as_uint(tf32r(a_[(rb + 8) * 36 + kc + 4]));
            }
            int nb = wn * 32 + (lane >> 2);
#pragma unroll
            for (int nt = 0; nt < 4; nt++) {
                int nc = nb + nt * 8;
                uint32_t bg[2], bu[2];
                bg[0] = __float_as_uint(tf32r(bg_[kc * 72 + nc]));
                bg[1] = __float_as_uint(tf32r(bg_[(kc + 4) * 72 + nc]));
                bu[0] = __float_as_uint(tf32r(bu_[kc * 72 + nc]));
                bu[1] = __float_as_uint(tf32r(bu_[(kc + 4) * 72 + nc]));
                mma_tf32(accG[0][nt], a[0], bg);
                mma_tf32(accG[1][nt], a[1], bg);
                mma_tf32(accU[0][nt], a[0], bu);
                mma_tf32(accU[1][nt], a[1], bu);
            }
        }
        __syncthreads();
    }

    // epilogue: silu(g) * u -> scratch A (gathered row order)
#pragma unroll
    for (int mt = 0; mt < 2; mt++) {
#pragma unroll
        for (int h = 0; h < 2; h++) {
            int gm = bm * 128 + wm * 32 + mt * 16 + (lane >> 2) + h * 8;
            if (gm >= cnt) continue;
#pragma unroll
            for (int nt = 0; nt < 4; nt++) {
                int col = bn * 64 + wn * 32 + nt * 8 + (lane & 3) * 2;
#pragma unroll
                for (int j = 0; j < 2; j++) {
                    float g = accG[mt][nt][h * 2 + j];
                    float u = accU[mt][nt][h * 2 + j];
                    g_A[(size_t)gm * I_DIM + col + j] = (g / (1.f + expf(-g))) * u;
                }
            }
        }
    }
}

// ---------------------------------------------------------------------------
// GEMM2 (gathered scatter): out[tok][h] (+)= cw[tok][e] * (A @ Wd)[gm][h]
// ---------------------------------------------------------------------------
template <bool ROUTED>
__global__ void __launch_bounds__(256) gemm2_kernel(const float* __restrict__ Wd,
                                                    int expert,
                                                    float* __restrict__ out) {
    int cnt = ROUTED ? g_cnt[expert] : N_TOK;
    int bm = blockIdx.y, bn = blockIdx.x;
    if (bm * 128 >= cnt) return;

    extern __shared__ float sm[];
    float* AsB = sm;                    // [2][128][36]
    float* BsB = sm + 2 * 128 * 36;     // [2][32][72]

    int tid = threadIdx.x, warp = tid >> 5, lane = tid & 31;
    int wm = warp & 3, wn = warp >> 2;

    const int* idx = g_idx + expert * N_TOK;
    int cbase = (tid & 7) * 4;
    const float* arow[4];
#pragma unroll
    for (int i = 0; i < 4; i++) {
        int r = (tid >> 3) + 32 * i;
        int gm = bm * 128 + r;
        int gg = gm < cnt ? gm : cnt - 1;
        arow[i] = g_A + (size_t)gg * I_DIM + cbase;
    }
    int wr = tid >> 4;
    int wc = (tid & 15) * 4;
    const float* wd0 = Wd + bn * 64 + wc;

    float acc[2][4][4] = {};

    auto issue = [&](int kt) {
        int st = kt & 1;
        float* a = AsB + st * 128 * 36;
#pragma unroll
        for (int i = 0; i < 4; i++) {
            int r = (tid >> 3) + 32 * i;
            cp_async16(a + r * 36 + cbase, arow[i] + kt * 32);
        }
        float* b = BsB + st * 32 * 72;
#pragma unroll
        for (int i = 0; i < 2; i++) {
            int r = wr + 16 * i;
            cp_async16(b + r * 72 + wc, wd0 + (size_t)(kt * 32 + r) * H_DIM);
        }
        cp_commit();
    };

    issue(0);
    const int KT = I_DIM / 32;
    for (int kt = 0; kt < KT; kt++) {
        if (kt + 1 < KT) { issue(kt + 1); cp_wait<1>(); }
        else             { cp_wait<0>(); }
        __syncthreads();
        int st = kt & 1;
        const float* a_ = AsB + st * 128 * 36;
        const float* b_ = BsB + st * 32 * 72;
#pragma unroll
        for (int ks = 0; ks < 4; ks++) {
            int kc = ks * 8 + (lane & 3);
            int r0 = wm * 32 + (lane >> 2);
            uint32_t a[2][4];
#pragma unroll
            for (int mt = 0; mt < 2; mt++) {
                int rb = r0 + mt * 16;
                a[mt][0] = __float_as_uint(tf32r(a_[rb * 36 + kc]));
                a[mt][1] = __float_as_uint(tf32r(a_[(rb + 8) * 36 + kc]));
                a[mt][2] = __float_as_uint(tf32r(a_[rb * 36 + kc + 4]));
                a[mt][3] = __float_as_uint(tf32r(a_[(rb + 8) * 36 + kc + 4]));
            }
            int nb = wn * 32 + (lane >> 2);
#pragma unroll
            for (int nt = 0; nt < 4; nt++) {
                int nc = nb + nt * 8;
                uint32_t b[2];
                b[0] = __float_as_uint(tf32r(b_[kc * 72 + nc]));
                b[1] = __float_as_uint(tf32r(b_[(kc + 4) * 72 + nc]));
                mma_tf32(acc[0][nt], a[0], b);
                mma_tf32(acc[1][nt], a[1], b);
            }
        }
        __syncthreads();
    }

#pragma unroll
    for (int mt = 0; mt < 2; mt++) {
#pragma unroll
        for (int h = 0; h < 2; h++) {
            int gm = bm * 128 + wm * 32 + mt * 16 + (lane >> 2) + h * 8;
            if (gm >= cnt) continue;
            int tok = ROUTED ? idx[gm] : gm;
            float s = ROUTED ? g_cw[(size_t)tok * E_NUM + expert] : 1.0f;
#pragma unroll
            for (int nt = 0; nt < 4; nt++) {
                int col = bn * 64 + wn * 32 + nt * 8 + (lane & 3) * 2;
#pragma unroll
                for (int j = 0; j < 2; j++) {
                    float v = s * acc[mt][nt][h * 2 + j];
                    size_t o = (size_t)tok * H_DIM + col + j;
                    if (ROUTED) out[o] += v;
                    else out[o] = v;
                }
            }
        }
    }
}

// ---------------------------------------------------------------------------
extern "C" void kernel_launch(void* const* d_in, const int* in_sizes, int n_in,
                              void* d_out, int out_size) {
    const float* x      = (const float*)d_in[0];
    const float* gate_w = (const float*)d_in[1];
    const float* bias   = (const float*)d_in[2];
    const float* Wg     = (const float*)d_in[3];
    const float* Wu     = (const float*)d_in[4];
    const float* Wd     = (const float*)d_in[5];
    const float* Wg_s   = (const float*)d_in[6];
    const float* Wu_s   = (const float*)d_in[7];
    const float* Wd_s   = (const float*)d_in[8];
    float* out = (float*)d_out;

    const int SMEM1 = (2 * 128 * 36 + 2 * 32 * 72 * 2) * 4;  // 73728
    const int SMEM2 = (2 * 128 * 36 + 2 * 32 * 72) * 4;      // 55296
    cudaFuncSetAttribute(gemm1_kernel<true>,  cudaFuncAttributeMaxDynamicSharedMemorySize, SMEM1);
    cudaFuncSetAttribute(gemm1_kernel<false>, cudaFuncAttributeMaxDynamicSharedMemorySize, SMEM1);
    cudaFuncSetAttribute(gemm2_kernel<true>,  cudaFuncAttributeMaxDynamicSharedMemorySize, SMEM2);
    cudaFuncSetAttribute(gemm2_kernel<false>, cudaFuncAttributeMaxDynamicSharedMemorySize, SMEM2);

    zero_cnt_kernel<<<1, 32>>>();
    router_kernel<<<N_TOK / 8, dim3(32, 8)>>>(x, gate_w, bias);

    dim3 g1(I_DIM / 64, N_TOK / 128);
    dim3 g2(H_DIM / 64, N_TOK / 128);

    // shared expert first (overwrites poisoned d_out)
    gemm1_kernel<false><<<g1, 256, SMEM1>>>(x, Wg_s, Wu_s, 0);
    gemm2_kernel<false><<<g2, 256, SMEM2>>>(Wd_s, 0, out);

    // routed experts (gathered) accumulate sequentially
    for (int e = 0; e < E_NUM; e++) {
        gemm1_kernel<true><<<g1, 256, SMEM1>>>(x, Wg + (size_t)e * H_DIM * I_DIM,
                                               Wu + (size_t)e * H_DIM * I_DIM, e);
        gemm2_kernel<true><<<g2, 256, SMEM2>>>(Wd + (size_t)e * I_DIM * H_DIM, e, out);
    }
}

// round 3
// speedup vs baseline: 2.2583x; 1.0695x over previous
#include <cuda_runtime.h>
#include <cstdint>

#define H_DIM 1024
#define I_DIM 512
#define E_NUM 8
#define N_TOK 8192
#define SCALE_F 2.5f

// Scratch (allocation-free rule: __device__ globals)
__device__ float g_A[(size_t)N_TOK * I_DIM];    // silu(g)*u, tf32-rounded
__device__ float g_cw[(size_t)N_TOK * E_NUM];   // dense combine weights
__device__ int   g_idx[E_NUM * N_TOK];          // per-expert gathered token lists
__device__ int   g_cnt[E_NUM];                  // per-expert token counts

// tf32-preconverted operands
__device__ float g_X32[(size_t)N_TOK * H_DIM];
__device__ float g_Wg32[(size_t)E_NUM * H_DIM * I_DIM];
__device__ float g_Wu32[(size_t)E_NUM * H_DIM * I_DIM];
__device__ float g_Wd32[(size_t)E_NUM * I_DIM * H_DIM];
__device__ float g_Wgs32[(size_t)H_DIM * I_DIM];
__device__ float g_Wus32[(size_t)H_DIM * I_DIM];
__device__ float g_Wds32[(size_t)I_DIM * H_DIM];

// ---------------------------------------------------------------------------
__device__ __forceinline__ float tf32r(float f) {
    uint32_t u;
    asm("cvt.rna.tf32.f32 %0, %1;" : "=r"(u) : "f"(f));
    return __uint_as_float(u);
}

__device__ __forceinline__ void mma_tf32(float c[4], const uint32_t a[4], const uint32_t b[2]) {
    asm volatile(
        "mma.sync.aligned.m16n8k8.row.col.f32.tf32.tf32.f32 "
        "{%0,%1,%2,%3}, {%4,%5,%6,%7}, {%8,%9}, {%0,%1,%2,%3};\n"
        : "+f"(c[0]), "+f"(c[1]), "+f"(c[2]), "+f"(c[3])
        : "r"(a[0]), "r"(a[1]), "r"(a[2]), "r"(a[3]), "r"(b[0]), "r"(b[1]));
}

__device__ __forceinline__ void cp_async16(float* smem, const float* gmem) {
    uint32_t s = (uint32_t)__cvta_generic_to_shared(smem);
    asm volatile("cp.async.cg.shared.global [%0], [%1], 16;\n" :: "r"(s), "l"(gmem));
}
__device__ __forceinline__ void cp_commit() { asm volatile("cp.async.commit_group;\n"); }
template <int N>
__device__ __forceinline__ void cp_wait() { asm volatile("cp.async.wait_group %0;\n" :: "n"(N)); }

// ---------------------------------------------------------------------------
__global__ void zero_cnt_kernel() {
    if (threadIdx.x < E_NUM) g_cnt[threadIdx.x] = 0;
}

// elementwise tf32 round (float4-vectorized, grid-stride)
__global__ void cvt_kernel(float* __restrict__ dst, const float* __restrict__ src, int n4) {
    int i = blockIdx.x * blockDim.x + threadIdx.x;
    int stride = gridDim.x * blockDim.x;
    for (; i < n4; i += stride) {
        float4 v = ((const float4*)src)[i];
        v.x = tf32r(v.x); v.y = tf32r(v.y); v.z = tf32r(v.z); v.w = tf32r(v.w);
        ((float4*)dst)[i] = v;
    }
}

// ---------------------------------------------------------------------------
// Router (reads raw f32 x for exact router math)
// ---------------------------------------------------------------------------
__global__ void router_kernel(const float* __restrict__ x,
                              const float* __restrict__ gate_w,
                              const float* __restrict__ bias) {
    int token = blockIdx.x * 8 + threadIdx.y;
    int lane = threadIdx.x;
    const float* xr = x + (size_t)token * H_DIM;

    float logits[E_NUM];
#pragma unroll
    for (int e = 0; e < E_NUM; e++) {
        const float* w = gate_w + (size_t)e * H_DIM;
        float s = 0.f;
        for (int h = lane; h < H_DIM; h += 32) s += xr[h] * w[h];
#pragma unroll
        for (int o = 16; o; o >>= 1) s += __shfl_xor_sync(0xffffffffu, s, o);
        logits[e] = s;
    }

    if (lane == 0) {
        float sc[E_NUM], scc[E_NUM];
#pragma unroll
        for (int e = 0; e < E_NUM; e++) {
            sc[e] = 1.f / (1.f + expf(-logits[e]));
            scc[e] = sc[e] + bias[e];
        }
        float gs[4];
#pragma unroll
        for (int g = 0; g < 4; g++) gs[g] = scc[2 * g] + scc[2 * g + 1];
        int g1 = 0;
#pragma unroll
        for (int g = 1; g < 4; g++) if (gs[g] > gs[g1]) g1 = g;
        int g2 = -1;
#pragma unroll
        for (int g = 0; g < 4; g++) {
            if (g == g1) continue;
            if (g2 < 0 || gs[g] > gs[g2]) g2 = g;
        }
        float w[E_NUM];
        float wsum = 0.f;
        bool sel[E_NUM];
#pragma unroll
        for (int e = 0; e < E_NUM; e++) {
            int g = e >> 1;
            sel[e] = (g == g1) || (g == g2);
            w[e] = sel[e] ? sc[e] : 0.f;
            wsum += w[e];
        }
        float inv = SCALE_F / (wsum + 1e-20f);
#pragma unroll
        for (int e = 0; e < E_NUM; e++) {
            g_cw[(size_t)token * E_NUM + e] = w[e] * inv;
            if (sel[e]) {
                int p = atomicAdd(&g_cnt[e], 1);
                g_idx[e * N_TOK + p] = token;
            }
        }
    }
}

// ---------------------------------------------------------------------------
// GEMM1 (dual): A[gm][i] = silu(X@Wg)*(X@Wu). 128x64x32 tiles, 2-stage, 1 sync.
// Operands pre-converted to tf32; inner loop is pure LDS+MMA.
// ---------------------------------------------------------------------------
template <bool GATHER>
__global__ void __launch_bounds__(256, 2) gemm1_kernel(const float* __restrict__ Wg,
                                                       const float* __restrict__ Wu,
                                                       int expert) {
    int cnt = GATHER ? g_cnt[expert] : N_TOK;
    int bm = blockIdx.y, bn = blockIdx.x;
    if (bm * 128 >= cnt) return;

    extern __shared__ float sm[];
    float* AsB = sm;                    // [2][128][36]
    float* BgB = sm + 2 * 128 * 36;     // [2][32][72]
    float* BuB = BgB + 2 * 32 * 72;     // [2][32][72]

    int tid = threadIdx.x, warp = tid >> 5, lane = tid & 31;
    int wm = warp & 3, wn = warp >> 2;

    const int* idx = g_idx + expert * N_TOK;
    int cbase = (tid & 7) * 4;
    const float* xrow[4];
#pragma unroll
    for (int i = 0; i < 4; i++) {
        int r = (tid >> 3) + 32 * i;
        int gm = bm * 128 + r;
        int gg = gm < cnt ? gm : cnt - 1;
        int tok = GATHER ? idx[gg] : gg;
        xrow[i] = g_X32 + (size_t)tok * H_DIM + cbase;
    }
    int wr = tid >> 4;           // 0..15
    int wc = (tid & 15) * 4;     // 0..60
    const float* wg0 = Wg + bn * 64 + wc;
    const float* wu0 = Wu + bn * 64 + wc;

    float accG[2][4][4] = {}, accU[2][4][4] = {};

    auto issue = [&](int kt) {
        int st = kt & 1;
        float* a = AsB + st * 128 * 36;
#pragma unroll
        for (int i = 0; i < 4; i++) {
            int r = (tid >> 3) + 32 * i;
            cp_async16(a + r * 36 + cbase, xrow[i] + kt * 32);
        }
        float* bg = BgB + st * 32 * 72;
        float* bu = BuB + st * 32 * 72;
#pragma unroll
        for (int i = 0; i < 2; i++) {
            int r = wr + 16 * i;
            cp_async16(bg + r * 72 + wc, wg0 + (size_t)(kt * 32 + r) * I_DIM);
            cp_async16(bu + r * 72 + wc, wu0 + (size_t)(kt * 32 + r) * I_DIM);
        }
        cp_commit();
    };

    issue(0);
    const int KT = H_DIM / 32;
    for (int kt = 0; kt < KT; kt++) {
        cp_wait<0>();
        __syncthreads();
        if (kt + 1 < KT) issue(kt + 1);   // writes buffer finished at kt-1 (guarded by sync)
        int st = kt & 1;
        const float* a_ = AsB + st * 128 * 36;
        const float* bg_ = BgB + st * 32 * 72;
        const float* bu_ = BuB + st * 32 * 72;
#pragma unroll
        for (int ks = 0; ks < 4; ks++) {
            int kc = ks * 8 + (lane & 3);
            int r0 = wm * 32 + (lane >> 2);
            uint32_t a[2][4];
#pragma unroll
            for (int mt = 0; mt < 2; mt++) {
                int rb = r0 + mt * 16;
                a[mt][0] = __float_as_uint(a_[rb * 36 + kc]);
                a[mt][1] = __float_as_uint(a_[(rb + 8) * 36 + kc]);
                a[mt][2] = __float_as_uint(a_[rb * 36 + kc + 4]);
                a[mt][3] = __float_as_uint(a_[(rb + 8) * 36 + kc + 4]);
            }
            int nb = wn * 32 + (lane >> 2);
#pragma unroll
            for (int nt = 0; nt < 4; nt++) {
                int nc = nb + nt * 8;
                uint32_t bg[2], bu[2];
                bg[0] = __float_as_uint(bg_[kc * 72 + nc]);
                bg[1] = __float_as_uint(bg_[(kc + 4) * 72 + nc]);
                bu[0] = __float_as_uint(bu_[kc * 72 + nc]);
                bu[1] = __float_as_uint(bu_[(kc + 4) * 72 + nc]);
                mma_tf32(accG[0][nt], a[0], bg);
                mma_tf32(accG[1][nt], a[1], bg);
                mma_tf32(accU[0][nt], a[0], bu);
                mma_tf32(accU[1][nt], a[1], bu);
            }
        }
    }

    // epilogue: silu(g)*u, tf32-rounded, -> g_A
#pragma unroll
    for (int mt = 0; mt < 2; mt++) {
#pragma unroll
        for (int h = 0; h < 2; h++) {
            int gm = bm * 128 + wm * 32 + mt * 16 + (lane >> 2) + h * 8;
            if (gm >= cnt) continue;
#pragma unroll
            for (int nt = 0; nt < 4; nt++) {
                int col = bn * 64 + wn * 32 + nt * 8 + (lane & 3) * 2;
#pragma unroll
                for (int j = 0; j < 2; j++) {
                    float g = accG[mt][nt][h * 2 + j];
                    float u = accU[mt][nt][h * 2 + j];
                    g_A[(size_t)gm * I_DIM + col + j] = tf32r((g / (1.f + expf(-g))) * u);
                }
            }
        }
    }
}

// ---------------------------------------------------------------------------
// GEMM2: out[tok][h] (+)= cw[tok][e] * (A @ Wd)[gm][h]
// ---------------------------------------------------------------------------
template <bool ROUTED>
__global__ void __launch_bounds__(256) gemm2_kernel(const float* __restrict__ Wd,
                                                    int expert,
                                                    float* __restrict__ out) {
    int cnt = ROUTED ? g_cnt[expert] : N_TOK;
    int bm = blockIdx.y, bn = blockIdx.x;
    if (bm * 128 >= cnt) return;

    extern __shared__ float sm[];
    float* AsB = sm;                    // [2][128][36]
    float* BsB = sm + 2 * 128 * 36;     // [2][32][72]

    int tid = threadIdx.x, warp = tid >> 5, lane = tid & 31;
    int wm = warp & 3, wn = warp >> 2;

    const int* idx = g_idx + expert * N_TOK;
    int cbase = (tid & 7) * 4;
    const float* arow[4];
#pragma unroll
    for (int i = 0; i < 4; i++) {
        int r = (tid >> 3) + 32 * i;
        int gm = bm * 128 + r;
        int gg = gm < cnt ? gm : cnt - 1;
        arow[i] = g_A + (size_t)gg * I_DIM + cbase;
    }
    int wr = tid >> 4;
    int wc = (tid & 15) * 4;
    const float* wd0 = Wd + bn * 64 + wc;

    float acc[2][4][4] = {};

    auto issue = [&](int kt) {
        int st = kt & 1;
        float* a = AsB + st * 128 * 36;
#pragma unroll
        for (int i = 0; i < 4; i++) {
            int r = (tid >> 3) + 32 * i;
            cp_async16(a + r * 36 + cbase, arow[i] + kt * 32);
        }
        float* b = BsB + st * 32 * 72;
#pragma unroll
        for (int i = 0; i < 2; i++) {
            int r = wr + 16 * i;
            cp_async16(b + r * 72 + wc, wd0 + (size_t)(kt * 32 + r) * H_DIM);
        }
        cp_commit();
    };

    issue(0);
    const int KT = I_DIM / 32;
    for (int kt = 0; kt < KT; kt++) {
        cp_wait<0>();
        __syncthreads();
        if (kt + 1 < KT) issue(kt + 1);
        int st = kt & 1;
        const float* a_ = AsB + st * 128 * 36;
        const float* b_ = BsB + st * 32 * 72;
#pragma unroll
        for (int ks = 0; ks < 4; ks++) {
            int kc = ks * 8 + (lane & 3);
            int r0 = wm * 32 + (lane >> 2);
            uint32_t a[2][4];
#pragma unroll
            for (int mt = 0; mt < 2; mt++) {
                int rb = r0 + mt * 16;
                a[mt][0] = __float_as_uint(a_[rb * 36 + kc]);
                a[mt][1] = __float_as_uint(a_[(rb + 8) * 36 + kc]);
                a[mt][2] = __float_as_uint(a_[rb * 36 + kc + 4]);
                a[mt][3] = __float_as_uint(a_[(rb + 8) * 36 + kc + 4]);
            }
            int nb = wn * 32 + (lane >> 2);
#pragma unroll
            for (int nt = 0; nt < 4; nt++) {
                int nc = nb + nt * 8;
                uint32_t b[2];
                b[0] = __float_as_uint(b_[kc * 72 + nc]);
                b[1] = __float_as_uint(b_[(kc + 4) * 72 + nc]);
                mma_tf32(acc[0][nt], a[0], b);
                mma_tf32(acc[1][nt], a[1], b);
            }
        }
    }

#pragma unroll
    for (int mt = 0; mt < 2; mt++) {
#pragma unroll
        for (int h = 0; h < 2; h++) {
            int gm = bm * 128 + wm * 32 + mt * 16 + (lane >> 2) + h * 8;
            if (gm >= cnt) continue;
            int tok = ROUTED ? idx[gm] : gm;
            float s = ROUTED ? g_cw[(size_t)tok * E_NUM + expert] : 1.0f;
#pragma unroll
            for (int nt = 0; nt < 4; nt++) {
                int col = bn * 64 + wn * 32 + nt * 8 + (lane & 3) * 2;
#pragma unroll
                for (int j = 0; j < 2; j++) {
                    float v = s * acc[mt][nt][h * 2 + j];
                    size_t o = (size_t)tok * H_DIM + col + j;
                    if (ROUTED) out[o] += v;
                    else out[o] = v;
                }
            }
        }
    }
}

// ---------------------------------------------------------------------------
extern "C" void kernel_launch(void* const* d_in, const int* in_sizes, int n_in,
                              void* d_out, int out_size) {
    const float* x      = (const float*)d_in[0];
    const float* gate_w = (const float*)d_in[1];
    const float* bias   = (const float*)d_in[2];
    const float* Wg     = (const float*)d_in[3];
    const float* Wu     = (const float*)d_in[4];
    const float* Wd     = (const float*)d_in[5];
    const float* Wg_s   = (const float*)d_in[6];
    const float* Wu_s   = (const float*)d_in[7];
    const float* Wd_s   = (const float*)d_in[8];
    float* out = (float*)d_out;

    const int SMEM1 = (2 * 128 * 36 + 2 * 32 * 72 * 2) * 4;  // 73728
    const int SMEM2 = (2 * 128 * 36 + 2 * 32 * 72) * 4;      // 55296
    cudaFuncSetAttribute(gemm1_kernel<true>,  cudaFuncAttributeMaxDynamicSharedMemorySize, SMEM1);
    cudaFuncSetAttribute(gemm1_kernel<false>, cudaFuncAttributeMaxDynamicSharedMemorySize, SMEM1);
    cudaFuncSetAttribute(gemm2_kernel<true>,  cudaFuncAttributeMaxDynamicSharedMemorySize, SMEM2);
    cudaFuncSetAttribute(gemm2_kernel<false>, cudaFuncAttributeMaxDynamicSharedMemorySize, SMEM2);

    // resolve device-global scratch addresses for cvt targets
    float *dX, *dWg, *dWu, *dWd, *dWgs, *dWus, *dWds;
    cudaGetSymbolAddress((void**)&dX,   g_X32);
    cudaGetSymbolAddress((void**)&dWg,  g_Wg32);
    cudaGetSymbolAddress((void**)&dWu,  g_Wu32);
    cudaGetSymbolAddress((void**)&dWd,  g_Wd32);
    cudaGetSymbolAddress((void**)&dWgs, g_Wgs32);
    cudaGetSymbolAddress((void**)&dWus, g_Wus32);
    cudaGetSymbolAddress((void**)&dWds, g_Wds32);

    zero_cnt_kernel<<<1, 32>>>();
    router_kernel<<<N_TOK / 8, dim3(32, 8)>>>(x, gate_w, bias);

    const int RW = E_NUM * H_DIM * I_DIM / 4;   // routed weight float4 count
    const int SW = H_DIM * I_DIM / 4;           // shared weight float4 count
    cvt_kernel<<<2048, 256>>>(dX,  x,    N_TOK * H_DIM / 4);
    cvt_kernel<<<2048, 256>>>(dWg, Wg,   RW);
    cvt_kernel<<<2048, 256>>>(dWu, Wu,   RW);
    cvt_kernel<<<2048, 256>>>(dWd, Wd,   RW);
    cvt_kernel<<<512,  256>>>(dWgs, Wg_s, SW);
    cvt_kernel<<<512,  256>>>(dWus, Wu_s, SW);
    cvt_kernel<<<512,  256>>>(dWds, Wd_s, SW);

    dim3 g1(I_DIM / 64, N_TOK / 128);
    dim3 g2(H_DIM / 64, N_TOK / 128);

    // shared expert first (overwrites poisoned d_out)
    gemm1_kernel<false><<<g1, 256, SMEM1>>>(dWgs, dWus, 0);
    gemm2_kernel<false><<<g2, 256, SMEM2>>>(dWds, 0, out);

    // routed experts (gathered) accumulate sequentially
    for (int e = 0; e < E_NUM; e++) {
        gemm1_kernel<true><<<g1, 256, SMEM1>>>(dWg + (size_t)e * H_DIM * I_DIM,
                                               dWu + (size_t)e * H_DIM * I_DIM, e);
        gemm2_kernel<true><<<g2, 256, SMEM2>>>(dWd + (size_t)e * I_DIM * H_DIM, e, out);
    }
}

// round 4
// speedup vs baseline: 2.5889x; 1.1464x over previous
#include <cuda_runtime.h>
#include <cstdint>

#define H_DIM 1024
#define I_DIM 512
#define E_NUM 8
#define N_TOK 8192
#define SCALE_F 2.5f

#define SA 40     // A smem row stride (floats) — conflict-free for LDS.64
#define SB 136    // B smem row stride (floats)

// ---------------- scratch (__device__ globals; allocation-free rule) -------
__device__ float g_A[(size_t)9 * N_TOK * I_DIM];      // gemm1 out, permuted A-layout
__device__ float g_Y[(size_t)9 * N_TOK * H_DIM];      // gemm2 partials per (expert,row)
__device__ float g_cw[(size_t)N_TOK * E_NUM];
__device__ int   g_idx[E_NUM * N_TOK];
__device__ int   g_cnt[E_NUM];
__device__ int   g_slot[N_TOK * 4];                   // token -> 4 (e*N_TOK+pos)

// tf32-preconverted, layout-permuted operands
__device__ float g_X32[(size_t)N_TOK * H_DIM];                  // A-permuted
__device__ float g_Wg32[(size_t)E_NUM * H_DIM * I_DIM];         // B pair-packed
__device__ float g_Wu32[(size_t)E_NUM * H_DIM * I_DIM];
__device__ float g_Wd32[(size_t)E_NUM * I_DIM * H_DIM];
__device__ float g_Wgs32[(size_t)H_DIM * I_DIM];
__device__ float g_Wus32[(size_t)H_DIM * I_DIM];
__device__ float g_Wds32[(size_t)I_DIM * H_DIM];

// ---------------------------------------------------------------------------
__device__ __forceinline__ float tf32r(float f) {
    uint32_t u;
    asm("cvt.rna.tf32.f32 %0, %1;" : "=r"(u) : "f"(f));
    return __uint_as_float(u);
}
__device__ __forceinline__ void mma_tf32(float c[4], const uint32_t a[4], const uint32_t b[2]) {
    asm volatile(
        "mma.sync.aligned.m16n8k8.row.col.f32.tf32.tf32.f32 "
        "{%0,%1,%2,%3}, {%4,%5,%6,%7}, {%8,%9}, {%0,%1,%2,%3};\n"
        : "+f"(c[0]), "+f"(c[1]), "+f"(c[2]), "+f"(c[3])
        : "r"(a[0]), "r"(a[1]), "r"(a[2]), "r"(a[3]), "r"(b[0]), "r"(b[1]));
}
__device__ __forceinline__ void cp_async16(float* smem, const float* gmem) {
    uint32_t s = (uint32_t)__cvta_generic_to_shared(smem);
    asm volatile("cp.async.cg.shared.global [%0], [%1], 16;\n" :: "r"(s), "l"(gmem));
}
__device__ __forceinline__ void cp_commit() { asm volatile("cp.async.commit_group;\n"); }
template <int N>
__device__ __forceinline__ void cp_wait() { asm volatile("cp.async.wait_group %0;\n" :: "n"(N)); }

// ---------------------------------------------------------------------------
__global__ void zero_cnt_kernel() {
    if (threadIdx.x < E_NUM) g_cnt[threadIdx.x] = 0;
}

// X: tf32-round + within-8-group A permutation: k -> 2*(k&3) + ((k>>2)&1)
__global__ void cvt_xp_kernel(float* __restrict__ dst, const float* __restrict__ src) {
    int i = blockIdx.x * blockDim.x + threadIdx.x;
    int stride = gridDim.x * blockDim.x;
    const int total = N_TOK * H_DIM;
    for (; i < total; i += stride) {
        int k = i & (H_DIM - 1);
        int p = (k & ~7) + 2 * (k & 3) + ((k >> 2) & 1);
        dst[(i & ~(H_DIM - 1)) + p] = tf32r(src[i]);
    }
}

// W: tf32-round + B pair-packed layout [kt][16][2N]
__global__ void cvt_wp_kernel(float* __restrict__ dst, const float* __restrict__ src,
                              int K, int N, int nT) {
    int i = blockIdx.x * blockDim.x + threadIdx.x;
    int stride = gridDim.x * blockDim.x;
    int per = K * N;
    int total = nT * per;
    for (; i < total; i += stride) {
        int t = i / per;
        int r = i - t * per;
        int k = r / N, n = r - (r / N) * N;
        int kt = k >> 5, kk = k & 31;
        int kp = (kk >> 3) * 4 + (kk & 3);
        int j = (kk >> 2) & 1;
        dst[(size_t)t * per + (size_t)kt * 32 * N + kp * 2 * N + n * 2 + j] = tf32r(src[i]);
    }
}

// ---------------------------------------------------------------------------
// Router (raw f32 math) + gather lists + per-token slots
// ---------------------------------------------------------------------------
__global__ void router_kernel(const float* __restrict__ x,
                              const float* __restrict__ gate_w,
                              const float* __restrict__ bias) {
    int token = blockIdx.x * 8 + threadIdx.y;
    int lane = threadIdx.x;
    const float* xr = x + (size_t)token * H_DIM;

    float logits[E_NUM];
#pragma unroll
    for (int e = 0; e < E_NUM; e++) {
        const float* w = gate_w + (size_t)e * H_DIM;
        float s = 0.f;
        for (int h = lane; h < H_DIM; h += 32) s += xr[h] * w[h];
#pragma unroll
        for (int o = 16; o; o >>= 1) s += __shfl_xor_sync(0xffffffffu, s, o);
        logits[e] = s;
    }

    if (lane == 0) {
        float sc[E_NUM], scc[E_NUM];
#pragma unroll
        for (int e = 0; e < E_NUM; e++) {
            sc[e] = 1.f / (1.f + expf(-logits[e]));
            scc[e] = sc[e] + bias[e];
        }
        float gs[4];
#pragma unroll
        for (int g = 0; g < 4; g++) gs[g] = scc[2 * g] + scc[2 * g + 1];
        int g1 = 0;
#pragma unroll
        for (int g = 1; g < 4; g++) if (gs[g] > gs[g1]) g1 = g;
        int g2 = -1;
#pragma unroll
        for (int g = 0; g < 4; g++) {
            if (g == g1) continue;
            if (g2 < 0 || gs[g] > gs[g2]) g2 = g;
        }
        float w[E_NUM];
        float wsum = 0.f;
        bool sel[E_NUM];
#pragma unroll
        for (int e = 0; e < E_NUM; e++) {
            int g = e >> 1;
            sel[e] = (g == g1) || (g == g2);
            w[e] = sel[e] ? sc[e] : 0.f;
            wsum += w[e];
        }
        float inv = SCALE_F / (wsum + 1e-20f);
        int s = 0;
#pragma unroll
        for (int e = 0; e < E_NUM; e++) {
            g_cw[(size_t)token * E_NUM + e] = w[e] * inv;
            if (sel[e]) {
                int p = atomicAdd(&g_cnt[e], 1);
                g_idx[e * N_TOK + p] = token;
                g_slot[token * 4 + s] = e * N_TOK + p;
                s++;
            }
        }
    }
}

// ---------------------------------------------------------------------------
// GEMM1_all: all 9 experts in one launch. grid = (8 ntiles, 64 mtiles, 9 experts)
// A[gm][i] = silu(X@Wg)*(X@Wu)   (output in permuted A-layout for gemm2)
// ---------------------------------------------------------------------------
__global__ void __launch_bounds__(256, 2) gemm1_all_kernel() {
    int e = blockIdx.z;
    bool gather = (e < E_NUM);
    int cnt = gather ? g_cnt[e] : N_TOK;
    int bm = blockIdx.y, bn = blockIdx.x;
    if (bm * 128 >= cnt) return;

    const float* Wg = gather ? g_Wg32 + (size_t)e * H_DIM * I_DIM : g_Wgs32;
    const float* Wu = gather ? g_Wu32 + (size_t)e * H_DIM * I_DIM : g_Wus32;

    extern __shared__ float sm[];
    float* AsB = sm;                       // [2][128][SA]
    float* BgB = sm + 2 * 128 * SA;        // [2][16][SB]
    float* BuB = BgB + 2 * 16 * SB;        // [2][16][SB]

    int tid = threadIdx.x, warp = tid >> 5, lane = tid & 31;
    int wm = warp & 3, wn = warp >> 2;

    const int* idx = g_idx + e * N_TOK;
    int cbase = (tid & 7) * 4;
    const float* xrow[4];
#pragma unroll
    for (int i = 0; i < 4; i++) {
        int r = (tid >> 3) + 32 * i;
        int gm = bm * 128 + r;
        int gg = gm < cnt ? gm : cnt - 1;
        int tok = gather ? idx[gg] : gg;
        xrow[i] = g_X32 + (size_t)tok * H_DIM + cbase;
    }
    // B loads: 512 chunks of 16B per matrix per k-tile -> 2 per thread
    int brow = tid >> 5;            // chunk c = tid + 256*i -> row = c>>5
    int bcol = (tid & 31) * 4;
    const float* wg0 = Wg + (size_t)brow * (2 * I_DIM) + bn * 128 + bcol;
    const float* wu0 = Wu + (size_t)brow * (2 * I_DIM) + bn * 128 + bcol;

    float accG[2][4][4] = {}, accU[2][4][4] = {};

    auto issue = [&](int kt) {
        int st = kt & 1;
        float* a = AsB + st * 128 * SA;
#pragma unroll
        for (int i = 0; i < 4; i++) {
            int r = (tid >> 3) + 32 * i;
            cp_async16(a + r * SA + cbase, xrow[i] + kt * 32);
        }
        float* bg = BgB + st * 16 * SB;
        float* bu = BuB + st * 16 * SB;
        size_t kadd = (size_t)kt * 32 * I_DIM;   // k-tile stride = 32*N floats
#pragma unroll
        for (int i = 0; i < 2; i++) {
            int r = brow + 8 * i;                // rows 0..15
            cp_async16(bg + r * SB + bcol, wg0 + kadd + (size_t)8 * i * (2 * I_DIM));
            cp_async16(bu + r * SB + bcol, wu0 + kadd + (size_t)8 * i * (2 * I_DIM));
        }
        cp_commit();
    };

    issue(0);
    const int KT = H_DIM / 32;
    for (int kt = 0; kt < KT; kt++) {
        cp_wait<0>();
        __syncthreads();
        if (kt + 1 < KT) issue(kt + 1);
        int st = kt & 1;
        const float* a_ = AsB + st * 128 * SA;
        const float* bg_ = BgB + st * 16 * SB;
        const float* bu_ = BuB + st * 16 * SB;
#pragma unroll
        for (int ks = 0; ks < 4; ks++) {
            int koff = ks * 8 + (lane & 3) * 2;
            int r0 = wm * 32 + (lane >> 2);
            float2 a00 = *(const float2*)&a_[r0 * SA + koff];
            float2 a01 = *(const float2*)&a_[(r0 + 8) * SA + koff];
            float2 a10 = *(const float2*)&a_[(r0 + 16) * SA + koff];
            float2 a11 = *(const float2*)&a_[(r0 + 24) * SA + koff];
            uint32_t a0[4] = {__float_as_uint(a00.x), __float_as_uint(a01.x),
                              __float_as_uint(a00.y), __float_as_uint(a01.y)};
            uint32_t a1[4] = {__float_as_uint(a10.x), __float_as_uint(a11.x),
                              __float_as_uint(a10.y), __float_as_uint(a11.y)};
            int br = ks * 4 + (lane & 3);
            int bc0 = (wn * 32 + (lane >> 2)) * 2;
#pragma unroll
            for (int nt = 0; nt < 4; nt++) {
                float2 g2 = *(const float2*)&bg_[br * SB + bc0 + nt * 16];
                float2 u2 = *(const float2*)&bu_[br * SB + bc0 + nt * 16];
                uint32_t bg2[2] = {__float_as_uint(g2.x), __float_as_uint(g2.y)};
                uint32_t bu2[2] = {__float_as_uint(u2.x), __float_as_uint(u2.y)};
                mma_tf32(accG[0][nt], a0, bg2);
                mma_tf32(accG[1][nt], a1, bg2);
                mma_tf32(accU[0][nt], a0, bu2);
                mma_tf32(accU[1][nt], a1, bu2);
            }
        }
    }

    // epilogue: silu(g)*u, tf32-rounded, permuted A-layout -> g_A segment e
    float* Aout = g_A + (size_t)e * N_TOK * I_DIM;
#pragma unroll
    for (int mt = 0; mt < 2; mt++) {
#pragma unroll
        for (int h = 0; h < 2; h++) {
            int gm = bm * 128 + wm * 32 + mt * 16 + (lane >> 2) + h * 8;
            if (gm >= cnt) continue;
#pragma unroll
            for (int nt = 0; nt < 4; nt++) {
                int col = bn * 64 + wn * 32 + nt * 8 + (lane & 3) * 2;
#pragma unroll
                for (int j = 0; j < 2; j++) {
                    int c = col + j;
                    int p = (c & ~7) + 2 * (c & 3) + ((c >> 2) & 1);
                    float g = accG[mt][nt][h * 2 + j];
                    float u = accU[mt][nt][h * 2 + j];
                    Aout[(size_t)gm * I_DIM + p] = tf32r((g / (1.f + expf(-g))) * u);
                }
            }
        }
    }
}

// ---------------------------------------------------------------------------
// GEMM2_all: g_Y[e*N_TOK+gm][h] = s * (A_e @ Wd_e)[gm][h]  (s = cw or 1)
// grid = (16 ntiles, 64 mtiles, 9 experts)
// ---------------------------------------------------------------------------
__global__ void __launch_bounds__(256, 2) gemm2_all_kernel() {
    int e = blockIdx.z;
    bool routed = (e < E_NUM);
    int cnt = routed ? g_cnt[e] : N_TOK;
    int bm = blockIdx.y, bn = blockIdx.x;
    if (bm * 128 >= cnt) return;

    const float* Wd = routed ? g_Wd32 + (size_t)e * I_DIM * H_DIM : g_Wds32;
    const float* Ain = g_A + (size_t)e * N_TOK * I_DIM;

    extern __shared__ float sm[];
    float* AsB = sm;                       // [2][128][SA]
    float* BsB = sm + 2 * 128 * SA;        // [2][16][SB]

    int tid = threadIdx.x, warp = tid >> 5, lane = tid & 31;
    int wm = warp & 3, wn = warp >> 2;

    const int* idx = g_idx + e * N_TOK;
    int cbase = (tid & 7) * 4;
    const float* arow[4];
#pragma unroll
    for (int i = 0; i < 4; i++) {
        int r = (tid >> 3) + 32 * i;
        int gm = bm * 128 + r;
        int gg = gm < cnt ? gm : cnt - 1;
        arow[i] = Ain + (size_t)gg * I_DIM + cbase;
    }
    int brow = tid >> 5;
    int bcol = (tid & 31) * 4;
    const float* wd0 = Wd + (size_t)brow * (2 * H_DIM) + bn * 128 + bcol;

    float acc[2][4][4] = {};

    auto issue = [&](int kt) {
        int st = kt & 1;
        float* a = AsB + st * 128 * SA;
#pragma unroll
        for (int i = 0; i < 4; i++) {
            int r = (tid >> 3) + 32 * i;
            cp_async16(a + r * SA + cbase, arow[i] + kt * 32);
        }
        float* b = BsB + st * 16 * SB;
        size_t kadd = (size_t)kt * 32 * H_DIM;
#pragma unroll
        for (int i = 0; i < 2; i++) {
            int r = brow + 8 * i;
            cp_async16(b + r * SB + bcol, wd0 + kadd + (size_t)8 * i * (2 * H_DIM));
        }
        cp_commit();
    };

    issue(0);
    const int KT = I_DIM / 32;
    for (int kt = 0; kt < KT; kt++) {
        cp_wait<0>();
        __syncthreads();
        if (kt + 1 < KT) issue(kt + 1);
        int st = kt & 1;
        const float* a_ = AsB + st * 128 * SA;
        const float* b_ = BsB + st * 16 * SB;
#pragma unroll
        for (int ks = 0; ks < 4; ks++) {
            int koff = ks * 8 + (lane & 3) * 2;
            int r0 = wm * 32 + (lane >> 2);
            float2 a00 = *(const float2*)&a_[r0 * SA + koff];
            float2 a01 = *(const float2*)&a_[(r0 + 8) * SA + koff];
            float2 a10 = *(const float2*)&a_[(r0 + 16) * SA + koff];
            float2 a11 = *(const float2*)&a_[(r0 + 24) * SA + koff];
            uint32_t a0[4] = {__float_as_uint(a00.x), __float_as_uint(a01.x),
                              __float_as_uint(a00.y), __float_as_uint(a01.y)};
            uint32_t a1[4] = {__float_as_uint(a10.x), __float_as_uint(a11.x),
                              __float_as_uint(a10.y), __float_as_uint(a11.y)};
            int br = ks * 4 + (lane & 3);
            int bc0 = (wn * 32 + (lane >> 2)) * 2;
#pragma unroll
            for (int nt = 0; nt < 4; nt++) {
                float2 b2 = *(const float2*)&b_[br * SB + bc0 + nt * 16];
                uint32_t bb[2] = {__float_as_uint(b2.x), __float_as_uint(b2.y)};
                mma_tf32(acc[0][nt], a0, bb);
                mma_tf32(acc[1][nt], a1, bb);
            }
        }
    }

    float* Yout = g_Y + (size_t)e * N_TOK * H_DIM;
#pragma unroll
    for (int mt = 0; mt < 2; mt++) {
#pragma unroll
        for (int h = 0; h < 2; h++) {
            int gm = bm * 128 + wm * 32 + mt * 16 + (lane >> 2) + h * 8;
            if (gm >= cnt) continue;
            float s = 1.0f;
            if (routed) {
                int tok = idx[gm];
                s = g_cw[(size_t)tok * E_NUM + e];
            }
#pragma unroll
            for (int nt = 0; nt < 4; nt++) {
                int col = bn * 64 + wn * 32 + nt * 8 + (lane & 3) * 2;
                float2 v;
                v.x = s * acc[mt][nt][h * 2 + 0];
                v.y = s * acc[mt][nt][h * 2 + 1];
                *(float2*)&Yout[(size_t)gm * H_DIM + col] = v;
            }
        }
    }
}

// ---------------------------------------------------------------------------
// Combine: out[tok] = Y_shared[tok] + sum_{s=0..3} Y[slot_s]  (ascending-e order)
// ---------------------------------------------------------------------------
__global__ void combine_kernel(float* __restrict__ out) {
    int tok = blockIdx.x;
    int t = threadIdx.x;   // 256 threads x float4 = 1024 floats
    int4 sl = *(const int4*)&g_slot[tok * 4];
    const float4* Y = (const float4*)g_Y;
    float4 acc = Y[((size_t)8 * N_TOK + tok) * (H_DIM / 4) + t];
    float4 v;
    v = Y[(size_t)sl.x * (H_DIM / 4) + t];
    acc.x += v.x; acc.y += v.y; acc.z += v.z; acc.w += v.w;
    v = Y[(size_t)sl.y * (H_DIM / 4) + t];
    acc.x += v.x; acc.y += v.y; acc.z += v.z; acc.w += v.w;
    v = Y[(size_t)sl.z * (H_DIM / 4) + t];
    acc.x += v.x; acc.y += v.y; acc.z += v.z; acc.w += v.w;
    v = Y[(size_t)sl.w * (H_DIM / 4) + t];
    acc.x += v.x; acc.y += v.y; acc.z += v.z; acc.w += v.w;
    ((float4*)out)[(size_t)tok * (H_DIM / 4) + t] = acc;
}

// ---------------------------------------------------------------------------
extern "C" void kernel_launch(void* const* d_in, const int* in_sizes, int n_in,
                              void* d_out, int out_size) {
    const float* x      = (const float*)d_in[0];
    const float* gate_w = (const float*)d_in[1];
    const float* bias   = (const float*)d_in[2];
    const float* Wg     = (const float*)d_in[3];
    const float* Wu     = (const float*)d_in[4];
    const float* Wd     = (const float*)d_in[5];
    const float* Wg_s   = (const float*)d_in[6];
    const float* Wu_s   = (const float*)d_in[7];
    const float* Wd_s   = (const float*)d_in[8];
    float* out = (float*)d_out;

    const int SMEM1 = (2 * 128 * SA + 2 * 16 * SB * 2) * 4;  // 75776
    const int SMEM2 = (2 * 128 * SA + 2 * 16 * SB) * 4;      // 58368
    cudaFuncSetAttribute(gemm1_all_kernel, cudaFuncAttributeMaxDynamicSharedMemorySize, SMEM1);
    cudaFuncSetAttribute(gemm2_all_kernel, cudaFuncAttributeMaxDynamicSharedMemorySize, SMEM2);

    float *dX, *dWg, *dWu, *dWd, *dWgs, *dWus, *dWds;
    cudaGetSymbolAddress((void**)&dX,   g_X32);
    cudaGetSymbolAddress((void**)&dWg,  g_Wg32);
    cudaGetSymbolAddress((void**)&dWu,  g_Wu32);
    cudaGetSymbolAddress((void**)&dWd,  g_Wd32);
    cudaGetSymbolAddress((void**)&dWgs, g_Wgs32);
    cudaGetSymbolAddress((void**)&dWus, g_Wus32);
    cudaGetSymbolAddress((void**)&dWds, g_Wds32);

    zero_cnt_kernel<<<1, 32>>>();
    router_kernel<<<N_TOK / 8, dim3(32, 8)>>>(x, gate_w, bias);

    cvt_xp_kernel<<<2048, 256>>>(dX, x);
    cvt_wp_kernel<<<4096, 256>>>(dWg, Wg, H_DIM, I_DIM, E_NUM);
    cvt_wp_kernel<<<4096, 256>>>(dWu, Wu, H_DIM, I_DIM, E_NUM);
    cvt_wp_kernel<<<4096, 256>>>(dWd, Wd, I_DIM, H_DIM, E_NUM);
    cvt_wp_kernel<<<512,  256>>>(dWgs, Wg_s, H_DIM, I_DIM, 1);
    cvt_wp_kernel<<<512,  256>>>(dWus, Wu_s, H_DIM, I_DIM, 1);
    cvt_wp_kernel<<<512,  256>>>(dWds, Wd_s, I_DIM, H_DIM, 1);

    gemm1_all_kernel<<<dim3(I_DIM / 64, N_TOK / 128, 9), 256, SMEM1>>>();
    gemm2_all_kernel<<<dim3(H_DIM / 64, N_TOK / 128, 9), 256, SMEM2>>>();
    combine_kernel<<<N_TOK, 256>>>(out);
}

// round 7
// speedup vs baseline: 4.8495x; 1.8732x over previous
#include <cuda_runtime.h>
#include <cuda_fp16.h>
#include <cstdint>

#define H_DIM 1024
#define I_DIM 512
#define E_NUM 8
#define N_TOK 8192
#define SCALE_F 2.5f

#define SROW 72                     // smem row stride (halves): 144B, ldmatrix conflict-free
#define A_SZ (128 * SROW)           // 9216 halves
#define B_SZ (64 * SROW)            // 4608 halves
#define ST1 (A_SZ + 2 * B_SZ)       // gemm1 stage halves
#define ST2 (A_SZ + B_SZ)           // gemm2 stage halves
#define SMEM1 (3 * ST1 * 2)         // 110592 B
#define SMEM2 (3 * ST2 * 2)         // 82944 B

// ---------------- scratch (__device__ globals; allocation-free rule) -------
__device__ __half g_A16[(size_t)9 * N_TOK * I_DIM];   // silu(g)*u, fp16
__device__ float  g_Y[(size_t)9 * N_TOK * H_DIM];     // gemm2 scaled partials
__device__ float  g_cw[(size_t)N_TOK * E_NUM];
__device__ int    g_idx[E_NUM * N_TOK];
__device__ int    g_cnt[E_NUM];
__device__ int    g_slot[N_TOK * 4];

// fp16 operands: X row-major [tok][H]; weights transposed to [n][k]
__device__ __half g_X16[(size_t)N_TOK * H_DIM];
__device__ __half g_WgT[(size_t)E_NUM * I_DIM * H_DIM];
__device__ __half g_WuT[(size_t)E_NUM * I_DIM * H_DIM];
__device__ __half g_WdT[(size_t)E_NUM * H_DIM * I_DIM];
__device__ __half g_WgsT[(size_t)I_DIM * H_DIM];
__device__ __half g_WusT[(size_t)I_DIM * H_DIM];
__device__ __half g_WdsT[(size_t)H_DIM * I_DIM];

// ---------------------------------------------------------------------------
__device__ __forceinline__ void cpa16(uint32_t saddr, const void* g) {
    asm volatile("cp.async.cg.shared.global [%0], [%1], 16;\n" :: "r"(saddr), "l"(g));
}
__device__ __forceinline__ void cp_commit() { asm volatile("cp.async.commit_group;\n"); }
template <int N>
__device__ __forceinline__ void cp_wait() { asm volatile("cp.async.wait_group %0;\n" :: "n"(N)); }

__device__ __forceinline__ void ldsm_x4(uint32_t r[4], uint32_t saddr) {
    asm volatile("ldmatrix.sync.aligned.m8n8.x4.shared.b16 {%0,%1,%2,%3}, [%4];"
                 : "=r"(r[0]), "=r"(r[1]), "=r"(r[2]), "=r"(r[3]) : "r"(saddr));
}
__device__ __forceinline__ void mma_f16(float c[4], const uint32_t a[4], const uint32_t b[2]) {
    asm volatile(
        "mma.sync.aligned.m16n8k16.row.col.f32.f16.f16.f32 "
        "{%0,%1,%2,%3}, {%4,%5,%6,%7}, {%8,%9}, {%0,%1,%2,%3};\n"
        : "+f"(c[0]), "+f"(c[1]), "+f"(c[2]), "+f"(c[3])
        : "r"(a[0]), "r"(a[1]), "r"(a[2]), "r"(a[3]), "r"(b[0]), "r"(b[1]));
}

// ---------------------------------------------------------------------------
__global__ void zero_cnt_kernel() {
    if (threadIdx.x < E_NUM) g_cnt[threadIdx.x] = 0;
}

// X f32 -> fp16
__global__ void cvt_x_kernel(__half* __restrict__ dst, const float* __restrict__ src, int n4) {
    int i = blockIdx.x * blockDim.x + threadIdx.x;
    int stride = gridDim.x * blockDim.x;
    for (; i < n4; i += stride) {
        float4 v = ((const float4*)src)[i];
        __half2 h0 = __floats2half2_rn(v.x, v.y);
        __half2 h1 = __floats2half2_rn(v.z, v.w);
        ((__half2*)dst)[2 * i]     = h0;
        ((__half2*)dst)[2 * i + 1] = h1;
    }
}

// transpose + fp16: dst[n][k] = (half)src[k][n]; grid (N/32, K/32, nMat), block (32,8)
__global__ void cvt_tr_kernel(__half* __restrict__ dst, const float* __restrict__ src,
                              int K, int N) {
    __shared__ float t[32][33];
    size_t base = (size_t)blockIdx.z * K * N;
    int kb = blockIdx.y * 32, nb = blockIdx.x * 32;
    int x = threadIdx.x, y = threadIdx.y;
#pragma unroll
    for (int i = 0; i < 32; i += 8)
        t[y + i][x] = src[base + (size_t)(kb + y + i) * N + nb + x];
    __syncthreads();
#pragma unroll
    for (int i = 0; i < 32; i += 8)
        dst[base + (size_t)(nb + y + i) * K + kb + x] = __float2half_rn(t[x][y + i]);
}

// ---------------------------------------------------------------------------
// Router (raw f32 math) + gather lists + per-token slots
// ---------------------------------------------------------------------------
__global__ void router_kernel(const float* __restrict__ x,
                              const float* __restrict__ gate_w,
                              const float* __restrict__ bias) {
    int token = blockIdx.x * 8 + threadIdx.y;
    int lane = threadIdx.x;
    const float* xr = x + (size_t)token * H_DIM;

    float logits[E_NUM];
#pragma unroll
    for (int e = 0; e < E_NUM; e++) {
        const float* w = gate_w + (size_t)e * H_DIM;
        float s = 0.f;
        for (int h = lane; h < H_DIM; h += 32) s += xr[h] * w[h];
#pragma unroll
        for (int o = 16; o; o >>= 1) s += __shfl_xor_sync(0xffffffffu, s, o);
        logits[e] = s;
    }

    if (lane == 0) {
        float sc[E_NUM], scc[E_NUM];
#pragma unroll
        for (int e = 0; e < E_NUM; e++) {
            sc[e] = 1.f / (1.f + expf(-logits[e]));
            scc[e] = sc[e] + bias[e];
        }
        float gs[4];
#pragma unroll
        for (int g = 0; g < 4; g++) gs[g] = scc[2 * g] + scc[2 * g + 1];
        int g1 = 0;
#pragma unroll
        for (int g = 1; g < 4; g++) if (gs[g] > gs[g1]) g1 = g;
        int g2 = -1;
#pragma unroll
        for (int g = 0; g < 4; g++) {
            if (g == g1) continue;
            if (g2 < 0 || gs[g] > gs[g2]) g2 = g;
        }
        float w[E_NUM];
        float wsum = 0.f;
        bool sel[E_NUM];
#pragma unroll
        for (int e = 0; e < E_NUM; e++) {
            int g = e >> 1;
            sel[e] = (g == g1) || (g == g2);
            w[e] = sel[e] ? sc[e] : 0.f;
            wsum += w[e];
        }
        float inv = SCALE_F / (wsum + 1e-20f);
        int s = 0;
#pragma unroll
        for (int e = 0; e < E_NUM; e++) {
            g_cw[(size_t)token * E_NUM + e] = w[e] * inv;
            if (sel[e]) {
                int p = atomicAdd(&g_cnt[e], 1);
                g_idx[e * N_TOK + p] = token;
                g_slot[token * 4 + s] = e * N_TOK + p;
                s++;
            }
        }
    }
}

// ---------------------------------------------------------------------------
// GEMM1 (fp16 mma, dual): 128x64 CTA tile, K-tile 64, 3-stage cp.async.
// grid (I/64=8, 64, 9), 256 threads (8 warps: 4m x 2n, warp 32x32).
// ---------------------------------------------------------------------------
__global__ void __launch_bounds__(256, 2) gemm1_all_kernel() {
    int e = blockIdx.z;
    bool gather = (e < E_NUM);
    int cnt = gather ? g_cnt[e] : N_TOK;
    int bm = blockIdx.y, bn = blockIdx.x;
    if (bm * 128 >= cnt) return;

    extern __shared__ __align__(16) char sh[];
    uint32_t sbase = (uint32_t)__cvta_generic_to_shared(sh);
    int tid = threadIdx.x, warp = tid >> 5, lane = tid & 31;
    int wm = warp & 3, wn = warp >> 2;

    const __half* Wg = gather ? g_WgT + (size_t)e * I_DIM * H_DIM : g_WgsT;
    const __half* Wu = gather ? g_WuT + (size_t)e * I_DIM * H_DIM : g_WusT;
    const int* idx = g_idx + e * N_TOK;

    int aj = (tid & 7) * 8;                 // 8-half chunk offset within row
    const __half* pA[4];
#pragma unroll
    for (int i = 0; i < 4; i++) {
        int r = (tid >> 3) + 32 * i;
        int gm = bm * 128 + r;
        int gg = gm < cnt ? gm : cnt - 1;
        int tok = gather ? idx[gg] : gg;
        pA[i] = g_X16 + (size_t)tok * H_DIM + aj;
    }
    const __half* pBg = Wg + (size_t)(bn * 64 + (tid >> 3)) * H_DIM + aj;
    const __half* pBu = Wu + (size_t)(bn * 64 + (tid >> 3)) * H_DIM + aj;

    uint32_t aoff  = ((wm * 32 + (lane & 7) + ((lane >> 3) & 1) * 8) * SROW + (lane >> 4) * 8) * 2;
    uint32_t boffg = (A_SZ + (wn * 32 + (lane & 7) + (lane >> 4) * 8) * SROW + ((lane >> 3) & 1) * 8) * 2;
    uint32_t boffu = boffg + B_SZ * 2;

    float accG[2][4][4] = {}, accU[2][4][4] = {};

    auto issue = [&](int kt, int st) {
        uint32_t b = sbase + st * (ST1 * 2);
        int ko = kt * 64;
#pragma unroll
        for (int i = 0; i < 4; i++) {
            int r = (tid >> 3) + 32 * i;
            cpa16(b + (r * SROW + aj) * 2, pA[i] + ko);
        }
#pragma unroll
        for (int i = 0; i < 2; i++) {
            int r = (tid >> 3) + 32 * i;
            cpa16(b + (A_SZ + r * SROW + aj) * 2, pBg + ko + (size_t)32 * i * H_DIM);
            cpa16(b + (A_SZ + B_SZ + r * SROW + aj) * 2, pBu + ko + (size_t)32 * i * H_DIM);
        }
        cp_commit();
    };

    const int KT = H_DIM / 64;   // 16
    issue(0, 0); issue(1, 1);
    for (int kt = 0; kt < KT; kt++) {
        // FIX (R6 race): on the final iteration only one group is outstanding,
        // so wait_group 1 would NOT guarantee tile kt landed. Drain fully.
        if (kt == KT - 1) cp_wait<0>(); else cp_wait<1>();
        __syncthreads();
        if (kt + 2 < KT) issue(kt + 2, (kt + 2) % 3);
        uint32_t stb = sbase + (kt % 3) * (ST1 * 2);
        uint32_t aA = stb + aoff, aG = stb + boffg, aU = stb + boffu;
#pragma unroll
        for (int ks = 0; ks < 4; ks++) {
            uint32_t a0[4], a1[4], qg0[4], qg1[4], qu0[4], qu1[4];
            ldsm_x4(a0, aA + ks * 32);
            ldsm_x4(a1, aA + 2304 + ks * 32);          // mt=1: 16*SROW*2
            ldsm_x4(qg0, aG + ks * 32);
            ldsm_x4(qg1, aG + 2304 + ks * 32);         // n 16..31
            ldsm_x4(qu0, aU + ks * 32);
            ldsm_x4(qu1, aU + 2304 + ks * 32);
            mma_f16(accG[0][0], a0, qg0 + 0); mma_f16(accG[1][0], a1, qg0 + 0);
            mma_f16(accG[0][1], a0, qg0 + 2); mma_f16(accG[1][1], a1, qg0 + 2);
            mma_f16(accG[0][2], a0, qg1 + 0); mma_f16(accG[1][2], a1, qg1 + 0);
            mma_f16(accG[0][3], a0, qg1 + 2); mma_f16(accG[1][3], a1, qg1 + 2);
            mma_f16(accU[0][0], a0, qu0 + 0); mma_f16(accU[1][0], a1, qu0 + 0);
            mma_f16(accU[0][1], a0, qu0 + 2); mma_f16(accU[1][1], a1, qu0 + 2);
            mma_f16(accU[0][2], a0, qu1 + 0); mma_f16(accU[1][2], a1, qu1 + 0);
            mma_f16(accU[0][3], a0, qu1 + 2); mma_f16(accU[1][3], a1, qu1 + 2);
        }
        __syncthreads();
    }

    // epilogue: silu(g)*u -> fp16 g_A16
    __half* Aout = g_A16 + (size_t)e * N_TOK * I_DIM;
#pragma unroll
    for (int mt = 0; mt < 2; mt++) {
#pragma unroll
        for (int h = 0; h < 2; h++) {
            int gm = bm * 128 + wm * 32 + mt * 16 + (lane >> 2) + h * 8;
            if (gm >= cnt) continue;
#pragma unroll
            for (int nt = 0; nt < 4; nt++) {
                int col = bn * 64 + wn * 32 + nt * 8 + (lane & 3) * 2;
                float g0 = accG[mt][nt][h * 2 + 0], u0 = accU[mt][nt][h * 2 + 0];
                float g1 = accG[mt][nt][h * 2 + 1], u1 = accU[mt][nt][h * 2 + 1];
                float v0 = (g0 / (1.f + expf(-g0))) * u0;
                float v1 = (g1 / (1.f + expf(-g1))) * u1;
                *(__half2*)(Aout + (size_t)gm * I_DIM + col) = __floats2half2_rn(v0, v1);
            }
        }
    }
}

// ---------------------------------------------------------------------------
// GEMM2 (fp16 mma): 128x64 CTA tile, K = I_DIM. grid (H/64=16, 64, 9).
// ---------------------------------------------------------------------------
__global__ void __launch_bounds__(256, 2) gemm2_all_kernel() {
    int e = blockIdx.z;
    bool routed = (e < E_NUM);
    int cnt = routed ? g_cnt[e] : N_TOK;
    int bm = blockIdx.y, bn = blockIdx.x;
    if (bm * 128 >= cnt) return;

    extern __shared__ __align__(16) char sh[];
    uint32_t sbase = (uint32_t)__cvta_generic_to_shared(sh);
    int tid = threadIdx.x, warp = tid >> 5, lane = tid & 31;
    int wm = warp & 3, wn = warp >> 2;

    const __half* Wd = routed ? g_WdT + (size_t)e * H_DIM * I_DIM : g_WdsT;
    const __half* Ain = g_A16 + (size_t)e * N_TOK * I_DIM;
    const int* idx = g_idx + e * N_TOK;

    int aj = (tid & 7) * 8;
    const __half* pA[4];
#pragma unroll
    for (int i = 0; i < 4; i++) {
        int r = (tid >> 3) + 32 * i;
        int gm = bm * 128 + r;
        int gg = gm < cnt ? gm : cnt - 1;
        pA[i] = Ain + (size_t)gg * I_DIM + aj;
    }
    const __half* pB = Wd + (size_t)(bn * 64 + (tid >> 3)) * I_DIM + aj;

    uint32_t aoff  = ((wm * 32 + (lane & 7) + ((lane >> 3) & 1) * 8) * SROW + (lane >> 4) * 8) * 2;
    uint32_t boff  = (A_SZ + (wn * 32 + (lane & 7) + (lane >> 4) * 8) * SROW + ((lane >> 3) & 1) * 8) * 2;

    float acc[2][4][4] = {};

    auto issue = [&](int kt, int st) {
        uint32_t b = sbase + st * (ST2 * 2);
        int ko = kt * 64;
#pragma unroll
        for (int i = 0; i < 4; i++) {
            int r = (tid >> 3) + 32 * i;
            cpa16(b + (r * SROW + aj) * 2, pA[i] + ko);
        }
#pragma unroll
        for (int i = 0; i < 2; i++) {
            int r = (tid >> 3) + 32 * i;
            cpa16(b + (A_SZ + r * SROW + aj) * 2, pB + ko + (size_t)32 * i * I_DIM);
        }
        cp_commit();
    };

    const int KT = I_DIM / 64;   // 8
    issue(0, 0); issue(1, 1);
    for (int kt = 0; kt < KT; kt++) {
        if (kt == KT - 1) cp_wait<0>(); else cp_wait<1>();   // FIX (R6 race)
        __syncthreads();
        if (kt + 2 < KT) issue(kt + 2, (kt + 2) % 3);
        uint32_t stb = sbase + (kt % 3) * (ST2 * 2);
        uint32_t aA = stb + aoff, aB = stb + boff;
#pragma unroll
        for (int ks = 0; ks < 4; ks++) {
            uint32_t a0[4], a1[4], q0[4], q1[4];
            ldsm_x4(a0, aA + ks * 32);
            ldsm_x4(a1, aA + 2304 + ks * 32);
            ldsm_x4(q0, aB + ks * 32);
            ldsm_x4(q1, aB + 2304 + ks * 32);
            mma_f16(acc[0][0], a0, q0 + 0); mma_f16(acc[1][0], a1, q0 + 0);
            mma_f16(acc[0][1], a0, q0 + 2); mma_f16(acc[1][1], a1, q0 + 2);
            mma_f16(acc[0][2], a0, q1 + 0); mma_f16(acc[1][2], a1, q1 + 0);
            mma_f16(acc[0][3], a0, q1 + 2); mma_f16(acc[1][3], a1, q1 + 2);
        }
        __syncthreads();
    }

    float* Yout = g_Y + (size_t)e * N_TOK * H_DIM;
#pragma unroll
    for (int mt = 0; mt < 2; mt++) {
#pragma unroll
        for (int h = 0; h < 2; h++) {
            int gm = bm * 128 + wm * 32 + mt * 16 + (lane >> 2) + h * 8;
            if (gm >= cnt) continue;
            float s = 1.0f;
            if (routed) s = g_cw[(size_t)idx[gm] * E_NUM + e];
#pragma unroll
            for (int nt = 0; nt < 4; nt++) {
                int col = bn * 64 + wn * 32 + nt * 8 + (lane & 3) * 2;
                float2 v;
                v.x = s * acc[mt][nt][h * 2 + 0];
                v.y = s * acc[mt][nt][h * 2 + 1];
                *(float2*)&Yout[(size_t)gm * H_DIM + col] = v;
            }
        }
    }
}

// ---------------------------------------------------------------------------
// Combine: out[tok] = Y_shared[tok] + sum of the token's 4 routed slots
// ---------------------------------------------------------------------------
__global__ void combine_kernel(float* __restrict__ out) {
    int tok = blockIdx.x;
    int t = threadIdx.x;
    int4 sl = *(const int4*)&g_slot[tok * 4];
    const float4* Y = (const float4*)g_Y;
    float4 acc = Y[((size_t)8 * N_TOK + tok) * (H_DIM / 4) + t];
    float4 v;
    v = Y[(size_t)sl.x * (H_DIM / 4) + t];
    acc.x += v.x; acc.y += v.y; acc.z += v.z; acc.w += v.w;
    v = Y[(size_t)sl.y * (H_DIM / 4) + t];
    acc.x += v.x; acc.y += v.y; acc.z += v.z; acc.w += v.w;
    v = Y[(size_t)sl.z * (H_DIM / 4) + t];
    acc.x += v.x; acc.y += v.y; acc.z += v.z; acc.w += v.w;
    v = Y[(size_t)sl.w * (H_DIM / 4) + t];
    acc.x += v.x; acc.y += v.y; acc.z += v.z; acc.w += v.w;
    ((float4*)out)[(size_t)tok * (H_DIM / 4) + t] = acc;
}

// ---------------------------------------------------------------------------
extern "C" void kernel_launch(void* const* d_in, const int* in_sizes, int n_in,
                              void* d_out, int out_size) {
    const float* x      = (const float*)d_in[0];
    const float* gate_w = (const float*)d_in[1];
    const float* bias   = (const float*)d_in[2];
    const float* Wg     = (const float*)d_in[3];
    const float* Wu     = (const float*)d_in[4];
    const float* Wd     = (const float*)d_in[5];
    const float* Wg_s   = (const float*)d_in[6];
    const float* Wu_s   = (const float*)d_in[7];
    const float* Wd_s   = (const float*)d_in[8];
    float* out = (float*)d_out;

    cudaFuncSetAttribute(gemm1_all_kernel, cudaFuncAttributeMaxDynamicSharedMemorySize, SMEM1);
    cudaFuncSetAttribute(gemm2_all_kernel, cudaFuncAttributeMaxDynamicSharedMemorySize, SMEM2);

    __half *dX, *dWg, *dWu, *dWd, *dWgs, *dWus, *dWds;
    cudaGetSymbolAddress((void**)&dX,   g_X16);
    cudaGetSymbolAddress((void**)&dWg,  g_WgT);
    cudaGetSymbolAddress((void**)&dWu,  g_WuT);
    cudaGetSymbolAddress((void**)&dWd,  g_WdT);
    cudaGetSymbolAddress((void**)&dWgs, g_WgsT);
    cudaGetSymbolAddress((void**)&dWus, g_WusT);
    cudaGetSymbolAddress((void**)&dWds, g_WdsT);

    zero_cnt_kernel<<<1, 32>>>();
    router_kernel<<<N_TOK / 8, dim3(32, 8)>>>(x, gate_w, bias);

    cvt_x_kernel<<<2048, 256>>>(dX, x, N_TOK * H_DIM / 4);
    dim3 tb(32, 8);
    cvt_tr_kernel<<<dim3(I_DIM / 32, H_DIM / 32, E_NUM), tb>>>(dWg, Wg, H_DIM, I_DIM);
    cvt_tr_kernel<<<dim3(I_DIM / 32, H_DIM / 32, E_NUM), tb>>>(dWu, Wu, H_DIM, I_DIM);
    cvt_tr_kernel<<<dim3(H_DIM / 32, I_DIM / 32, E_NUM), tb>>>(dWd, Wd, I_DIM, H_DIM);
    cvt_tr_kernel<<<dim3(I_DIM / 32, H_DIM / 32, 1), tb>>>(dWgs, Wg_s, H_DIM, I_DIM);
    cvt_tr_kernel<<<dim3(I_DIM / 32, H_DIM / 32, 1), tb>>>(dWus, Wu_s, H_DIM, I_DIM);
    cvt_tr_kernel<<<dim3(H_DIM / 32, I_DIM / 32, 1), tb>>>(dWds, Wd_s, I_DIM, H_DIM);

    gemm1_all_kernel<<<dim3(I_DIM / 64, N_TOK / 128, 9), 256, SMEM1>>>();
    gemm2_all_kernel<<<dim3(H_DIM / 64, N_TOK / 128, 9), 256, SMEM2>>>();
    combine_kernel<<<N_TOK, 256>>>(out);
}